// round 1
// baseline (speedup 1.0000x reference)
#include <cuda_runtime.h>

#define N_NODES 100000
#define N_EDGES 3200000
#define TOT_E   (N_EDGES + N_NODES)
#define HID     32
#define NEG     0.2f
#define ENC_NEGINF 0x007FFFFFu

// ---- scratch (static device allocations; no cudaMalloc allowed) ----
__device__ float    g_h[N_NODES * HID];    // current dense features (layer input to edge passes)
__device__ float    g_acc[N_NODES * HID];  // sum of ex * h[src]
__device__ float    g_x2[N_NODES * HID];   // layer-1 output (layer-2 input)
__device__ float    g_as[N_NODES];         // per-node att_src half
__device__ float    g_ad[N_NODES];         // per-node att_dst half
__device__ unsigned g_menc[N_NODES];       // encoded running max of logits per dst
__device__ float    g_den[N_NODES];        // sum of ex per dst

// order-preserving float<->uint encoding for atomicMax
__device__ __forceinline__ unsigned encf(float f) {
    unsigned u = __float_as_uint(f);
    return (u & 0x80000000u) ? ~u : (u | 0x80000000u);
}
__device__ __forceinline__ float decf(unsigned u) {
    return (u & 0x80000000u) ? __uint_as_float(u ^ 0x80000000u)
                             : __uint_as_float(~u);
}

__device__ __forceinline__ float lrelu(float x) { return x >= 0.f ? x : NEG * x; }

// ---------------------------------------------------------------------------
// Layer 1 transform: h = x @ W1; a_s/a_d per node; init max/den/acc.
// One warp per node. x is [N,3], W1 is [3,32] row-major.
// ---------------------------------------------------------------------------
__global__ void __launch_bounds__(256) k_transform1(
    const float* __restrict__ x, const float* __restrict__ W1,
    const float* __restrict__ aw_s, const float* __restrict__ aw_d)
{
    int warp = (blockIdx.x * 256 + threadIdx.x) >> 5;
    int lane = threadIdx.x & 31;
    if (warp >= N_NODES) return;

    float xv = (lane < 3) ? x[warp * 3 + lane] : 0.f;
    float x0 = __shfl_sync(0xffffffffu, xv, 0);
    float x1 = __shfl_sync(0xffffffffu, xv, 1);
    float x2 = __shfl_sync(0xffffffffu, xv, 2);

    float h = x0 * W1[lane] + x1 * W1[HID + lane] + x2 * W1[2 * HID + lane];
    g_h[warp * HID + lane] = h;
    g_acc[warp * HID + lane] = 0.f;

    float s = h * aw_s[lane];
    float d = h * aw_d[lane];
#pragma unroll
    for (int o = 16; o; o >>= 1) {
        s += __shfl_xor_sync(0xffffffffu, s, o);
        d += __shfl_xor_sync(0xffffffffu, d, o);
    }
    if (lane == 0) {
        g_as[warp] = s;
        g_ad[warp] = d;
        g_menc[warp] = ENC_NEGINF;
        g_den[warp] = 0.f;
    }
}

// ---------------------------------------------------------------------------
// Layer 2 transform: h = x2 @ W2 (32x32 via smem + shfl broadcast); same inits.
// ---------------------------------------------------------------------------
__global__ void __launch_bounds__(256) k_transform2(
    const float* __restrict__ W2,
    const float* __restrict__ aw_s, const float* __restrict__ aw_d)
{
    __shared__ float sW2[HID * HID];
    for (int i = threadIdx.x; i < HID * HID; i += 256) sW2[i] = W2[i];
    __syncthreads();

    int warp = (blockIdx.x * 256 + threadIdx.x) >> 5;
    int lane = threadIdx.x & 31;
    if (warp >= N_NODES) return;

    float xv = g_x2[warp * HID + lane];
    float h = 0.f;
#pragma unroll
    for (int i = 0; i < HID; i++)
        h += __shfl_sync(0xffffffffu, xv, i) * sW2[i * HID + lane];

    g_h[warp * HID + lane] = h;
    g_acc[warp * HID + lane] = 0.f;

    float s = h * aw_s[lane];
    float d = h * aw_d[lane];
#pragma unroll
    for (int o = 16; o; o >>= 1) {
        s += __shfl_xor_sync(0xffffffffu, s, o);
        d += __shfl_xor_sync(0xffffffffu, d, o);
    }
    if (lane == 0) {
        g_as[warp] = s;
        g_ad[warp] = d;
        g_menc[warp] = ENC_NEGINF;
        g_den[warp] = 0.f;
    }
}

// ---------------------------------------------------------------------------
// Edge pass 1: segment max of leaky-relu logits via encoded atomicMax.
// Thread per edge; last N_NODES "edges" are the implicit self-loops.
// ---------------------------------------------------------------------------
__global__ void __launch_bounds__(256) k_max(
    const int* __restrict__ src, const int* __restrict__ dst)
{
    int e = blockIdx.x * 256 + threadIdx.x;
    if (e >= TOT_E) return;
    int s, d;
    if (e < N_EDGES) { s = src[e]; d = dst[e]; }
    else             { s = d = e - N_EDGES; }
    float l = lrelu(g_as[s] + g_ad[d]);
    atomicMax(&g_menc[d], encf(l));
}

// ---------------------------------------------------------------------------
// Edge pass 2: ex = exp(logit - m[dst]); den[dst] += ex;
// acc[dst][:] += ex * h[src][:]  (warp-cooperative: 32 edges/warp, then a
// broadcast loop so each edge's 32-feature gather and RED are fully coalesced)
// ---------------------------------------------------------------------------
__global__ void __launch_bounds__(256) k_agg(
    const int* __restrict__ src, const int* __restrict__ dst)
{
    int warp = (blockIdx.x * 256 + threadIdx.x) >> 5;
    int lane = threadIdx.x & 31;
    int e = warp * 32 + lane;

    int s = 0, d = 0;
    float ex = 0.f;
    int valid = (e < TOT_E);
    if (valid) {
        if (e < N_EDGES) { s = src[e]; d = dst[e]; }
        else             { s = d = e - N_EDGES; }
        float l = lrelu(g_as[s] + g_ad[d]);
        float m = decf(g_menc[d]);
        ex = __expf(l - m);
        atomicAdd(&g_den[d], ex);
    }
    unsigned vm = __ballot_sync(0xffffffffu, valid);

#pragma unroll 8
    for (int j = 0; j < 32; j++) {
        if (!((vm >> j) & 1u)) continue;
        int   se  = __shfl_sync(0xffffffffu, s, j);
        int   de  = __shfl_sync(0xffffffffu, d, j);
        float exe = __shfl_sync(0xffffffffu, ex, j);
        atomicAdd(&g_acc[de * HID + lane], exe * g_h[se * HID + lane]);
    }
}

// ---------------------------------------------------------------------------
// Layer 1 epilogue: x2 = relu(acc / (den + 1e-16) + b1)
// Thread per (node, feature).
// ---------------------------------------------------------------------------
__global__ void __launch_bounds__(256) k_norm1(const float* __restrict__ b1)
{
    int idx = blockIdx.x * 256 + threadIdx.x;
    if (idx >= N_NODES * HID) return;
    int n = idx >> 5;
    int k = idx & 31;
    float v = g_acc[idx] / (g_den[n] + 1e-16f) + b1[k];
    g_x2[idx] = v > 0.f ? v : 0.f;
}

// ---------------------------------------------------------------------------
// Layer 2 epilogue fused with linear head:
// out[n] = dot(relu(acc/(den+eps) + b2), Wl) + bl.  One warp per node.
// ---------------------------------------------------------------------------
__global__ void __launch_bounds__(256) k_norm2_final(
    const float* __restrict__ b2, const float* __restrict__ Wl,
    const float* __restrict__ bl, float* __restrict__ out)
{
    int warp = (blockIdx.x * 256 + threadIdx.x) >> 5;
    int lane = threadIdx.x & 31;
    if (warp >= N_NODES) return;
    float v = g_acc[warp * HID + lane] / (g_den[warp] + 1e-16f) + b2[lane];
    v = v > 0.f ? v : 0.f;
    float p = v * Wl[lane];
#pragma unroll
    for (int o = 16; o; o >>= 1) p += __shfl_xor_sync(0xffffffffu, p, o);
    if (lane == 0) out[warp] = p + bl[0];
}

// ---------------------------------------------------------------------------
extern "C" void kernel_launch(void* const* d_in, const int* in_sizes, int n_in,
                              void* d_out, int out_size)
{
    const float* x     = (const float*)d_in[0];
    const int*   eidx  = (const int*)d_in[1];     // [2, E]
    const float* W1    = (const float*)d_in[2];
    const float* as1   = (const float*)d_in[3];
    const float* ad1   = (const float*)d_in[4];
    const float* b1    = (const float*)d_in[5];
    const float* W2    = (const float*)d_in[6];
    const float* as2   = (const float*)d_in[7];
    const float* ad2   = (const float*)d_in[8];
    const float* b2    = (const float*)d_in[9];
    const float* Wl    = (const float*)d_in[10];
    const float* bl    = (const float*)d_in[11];
    float*       out   = (float*)d_out;

    const int* src = eidx;
    const int* dst = eidx + N_EDGES;

    const int nodeWarpBlocks = (N_NODES + 7) / 8;           // 8 warps/block
    const int edgeBlocks     = (TOT_E + 255) / 256;
    const int aggBlocks      = ((TOT_E + 31) / 32 + 7) / 8; // 8 warps/block
    const int nfBlocks       = (N_NODES * HID + 255) / 256;

    // ---- layer 1 ----
    k_transform1<<<nodeWarpBlocks, 256>>>(x, W1, as1, ad1);
    k_max<<<edgeBlocks, 256>>>(src, dst);
    k_agg<<<aggBlocks, 256>>>(src, dst);
    k_norm1<<<nfBlocks, 256>>>(b1);

    // ---- layer 2 ----
    k_transform2<<<nodeWarpBlocks, 256>>>(W2, as2, ad2);
    k_max<<<edgeBlocks, 256>>>(src, dst);
    k_agg<<<aggBlocks, 256>>>(src, dst);
    k_norm2_final<<<nodeWarpBlocks, 256>>>(b2, Wl, bl, out);
}

// round 2
// speedup vs baseline: 1.4511x; 1.4511x over previous
#include <cuda_runtime.h>

#define N_NODES 100000
#define N_EDGES 3200000
#define TOT_E   (N_EDGES + N_NODES)
#define HID     32
#define NEG     0.2f
#define ENC_NEGINF 0x007FFFFFu

// ---- static device scratch (no cudaMalloc allowed) ----
__device__ __align__(16) float g_h[N_NODES * HID];    // dense features for edge passes
__device__ __align__(16) float g_acc[N_NODES * HID];  // sum of ex * h[src]
__device__ float    g_as[N_NODES];    // per-node att_src half
__device__ float    g_ad[N_NODES];    // per-node att_dst half
__device__ float    g_den[N_NODES];   // sum of ex per dst
__device__ unsigned g_amax_enc[2];    // encoded global max of a_s, one slot per layer

// order-preserving float<->uint encoding for atomicMax
__device__ __forceinline__ unsigned encf(float f) {
    unsigned u = __float_as_uint(f);
    return (u & 0x80000000u) ? ~u : (u | 0x80000000u);
}
__device__ __forceinline__ float decf(unsigned u) {
    return (u & 0x80000000u) ? __uint_as_float(u ^ 0x80000000u)
                             : __uint_as_float(~u);
}
__device__ __forceinline__ float lrelu(float x) { return x >= 0.f ? x : NEG * x; }

__device__ __forceinline__ void red_add_v4(float* p, float4 v) {
    asm volatile("red.global.add.v4.f32 [%0], {%1,%2,%3,%4};"
                 :: "l"(p), "f"(v.x), "f"(v.y), "f"(v.z), "f"(v.w) : "memory");
}

// block-level max of per-warp a_s values -> atomicMax into g_amax_enc[slot]
__device__ __forceinline__ void block_amax(float s_lane0, int lane, int wid, int slot) {
    __shared__ float warp_s[8];
    if (lane == 0) warp_s[wid] = s_lane0;
    __syncthreads();
    if (wid == 0 && lane == 0) {
        float m = warp_s[0];
#pragma unroll
        for (int i = 1; i < 8; i++) m = fmaxf(m, warp_s[i]);
        atomicMax(&g_amax_enc[slot], encf(m));
    }
}

// ---------------------------------------------------------------------------
__global__ void k_init() {
    g_amax_enc[0] = ENC_NEGINF;
    g_amax_enc[1] = ENC_NEGINF;
}

// ---------------------------------------------------------------------------
// Layer 1 transform: h = x @ W1; a_s/a_d per node; acc=0, den=0; amax slot 0.
// One warp per node.
// ---------------------------------------------------------------------------
__global__ void __launch_bounds__(256) k_transform1(
    const float* __restrict__ x, const float* __restrict__ W1,
    const float* __restrict__ aw_s, const float* __restrict__ aw_d)
{
    int wid  = threadIdx.x >> 5;
    int lane = threadIdx.x & 31;
    int node = blockIdx.x * 8 + wid;

    float s = -3.4e38f;
    if (node < N_NODES) {
        float xv = (lane < 3) ? x[node * 3 + lane] : 0.f;
        float x0 = __shfl_sync(0xffffffffu, xv, 0);
        float x1 = __shfl_sync(0xffffffffu, xv, 1);
        float x2 = __shfl_sync(0xffffffffu, xv, 2);

        float h = x0 * W1[lane] + x1 * W1[HID + lane] + x2 * W1[2 * HID + lane];
        g_h[node * HID + lane]   = h;
        g_acc[node * HID + lane] = 0.f;

        s = h * aw_s[lane];
        float d = h * aw_d[lane];
#pragma unroll
        for (int o = 16; o; o >>= 1) {
            s += __shfl_xor_sync(0xffffffffu, s, o);
            d += __shfl_xor_sync(0xffffffffu, d, o);
        }
        if (lane == 0) {
            g_as[node]  = s;
            g_ad[node]  = d;
            g_den[node] = 0.f;
        }
    }
    block_amax(s, lane, wid, 0);
}

// ---------------------------------------------------------------------------
// Fused layer-1 epilogue + layer-2 transform:
// x2 = relu(acc/(den+eps) + b1);  h = x2 @ W2;  a_s/a_d;  acc=0, den=0; amax slot 1.
// ---------------------------------------------------------------------------
__global__ void __launch_bounds__(256) k_norm1_transform2(
    const float* __restrict__ b1, const float* __restrict__ W2,
    const float* __restrict__ aw_s, const float* __restrict__ aw_d)
{
    __shared__ float sW2[HID * HID];
    for (int i = threadIdx.x; i < HID * HID; i += 256) sW2[i] = W2[i];
    __syncthreads();

    int wid  = threadIdx.x >> 5;
    int lane = threadIdx.x & 31;
    int node = blockIdx.x * 8 + wid;

    float s = -3.4e38f;
    if (node < N_NODES) {
        float v = g_acc[node * HID + lane] / (g_den[node] + 1e-16f) + b1[lane];
        v = v > 0.f ? v : 0.f;

        float h = 0.f;
#pragma unroll
        for (int i = 0; i < HID; i++)
            h += __shfl_sync(0xffffffffu, v, i) * sW2[i * HID + lane];

        g_h[node * HID + lane]   = h;
        g_acc[node * HID + lane] = 0.f;

        s = h * aw_s[lane];
        float d = h * aw_d[lane];
#pragma unroll
        for (int o = 16; o; o >>= 1) {
            s += __shfl_xor_sync(0xffffffffu, s, o);
            d += __shfl_xor_sync(0xffffffffu, d, o);
        }
        if (lane == 0) {
            g_as[node]  = s;
            g_ad[node]  = d;
            g_den[node] = 0.f;
        }
    }
    block_amax(s, lane, wid, 1);
}

// ---------------------------------------------------------------------------
// Fused edge pass: ex = exp(lrelu(as+ad) - lrelu(Amax+ad));  den[d] += ex;
// acc[d][:] += ex * h[s][:]  via 4-edges-in-flight x (8 lanes * float4) v4 REDs.
// Last N_NODES indices are the implicit self-loops.
// ---------------------------------------------------------------------------
template<int SLOT>
__global__ void __launch_bounds__(256) k_agg(
    const int* __restrict__ src, const int* __restrict__ dst)
{
    const float Amax = decf(g_amax_enc[SLOT]);

    int warp = (blockIdx.x * 256 + threadIdx.x) >> 5;
    int lane = threadIdx.x & 31;
    int e = warp * 32 + lane;

    int s = 0, d = 0;
    float ex = 0.f;
    int valid = (e < TOT_E);
    if (valid) {
        if (e < N_EDGES) { s = src[e]; d = dst[e]; }
        else             { s = d = e - N_EDGES; }
        float as = g_as[s];
        float ad = g_ad[d];
        float l = lrelu(as + ad);
        float m = lrelu(Amax + ad);     // per-dst upper bound on all incoming logits
        ex = __expf(l - m);
        atomicAdd(&g_den[d], ex);
    }
    unsigned vm = __ballot_sync(0xffffffffu, valid);

    int grp = lane >> 3;   // 0..3 : which of 4 concurrent edges
    int mem = lane & 7;    // 0..7 : float4 chunk within 32 features

#pragma unroll
    for (int it = 0; it < 8; it++) {
        int j = it * 4 + grp;   // source lane holding this group's edge
        int   se  = __shfl_sync(0xffffffffu, s, j);
        int   de  = __shfl_sync(0xffffffffu, d, j);
        float exe = __shfl_sync(0xffffffffu, ex, j);
        if ((vm >> j) & 1u) {
            const float4 hv = *reinterpret_cast<const float4*>(&g_h[se * HID + mem * 4]);
            float4 v = make_float4(exe * hv.x, exe * hv.y, exe * hv.z, exe * hv.w);
            red_add_v4(&g_acc[de * HID + mem * 4], v);
        }
    }
}

// ---------------------------------------------------------------------------
// Layer-2 epilogue fused with linear head:
// out[n] = dot(relu(acc/(den+eps) + b2), Wl) + bl.  One warp per node.
// ---------------------------------------------------------------------------
__global__ void __launch_bounds__(256) k_norm2_final(
    const float* __restrict__ b2, const float* __restrict__ Wl,
    const float* __restrict__ bl, float* __restrict__ out)
{
    int warp = (blockIdx.x * 256 + threadIdx.x) >> 5;
    int lane = threadIdx.x & 31;
    if (warp >= N_NODES) return;
    float v = g_acc[warp * HID + lane] / (g_den[warp] + 1e-16f) + b2[lane];
    v = v > 0.f ? v : 0.f;
    float p = v * Wl[lane];
#pragma unroll
    for (int o = 16; o; o >>= 1) p += __shfl_xor_sync(0xffffffffu, p, o);
    if (lane == 0) out[warp] = p + bl[0];
}

// ---------------------------------------------------------------------------
extern "C" void kernel_launch(void* const* d_in, const int* in_sizes, int n_in,
                              void* d_out, int out_size)
{
    const float* x   = (const float*)d_in[0];
    const int*  eidx = (const int*)d_in[1];     // [2, E]
    const float* W1  = (const float*)d_in[2];
    const float* as1 = (const float*)d_in[3];
    const float* ad1 = (const float*)d_in[4];
    const float* b1  = (const float*)d_in[5];
    const float* W2  = (const float*)d_in[6];
    const float* as2 = (const float*)d_in[7];
    const float* ad2 = (const float*)d_in[8];
    const float* b2  = (const float*)d_in[9];
    const float* Wl  = (const float*)d_in[10];
    const float* bl  = (const float*)d_in[11];
    float*       out = (float*)d_out;

    const int* src = eidx;
    const int* dst = eidx + N_EDGES;

    const int nodeBlocks = (N_NODES + 7) / 8;               // 8 warps/block, warp/node
    const int aggBlocks  = ((TOT_E + 31) / 32 + 7) / 8;     // 8 warps/block, 32 edges/warp

    k_init<<<1, 32>>>();

    // ---- layer 1 ----
    k_transform1<<<nodeBlocks, 256>>>(x, W1, as1, ad1);
    k_agg<0><<<aggBlocks, 256>>>(src, dst);

    // ---- layer 2 (epilogue of layer 1 fused in) ----
    k_norm1_transform2<<<nodeBlocks, 256>>>(b1, W2, as2, ad2);
    k_agg<1><<<aggBlocks, 256>>>(src, dst);

    k_norm2_final<<<nodeBlocks, 256>>>(b2, Wl, bl, out);
}

// round 3
// speedup vs baseline: 1.6149x; 1.1129x over previous
#include <cuda_runtime.h>
#include <cuda_fp16.h>

#define N_NODES 100000
#define N_EDGES 3200000
#define HID     32
#define NEG     0.2f
#define ENC_NEGINF 0x007FFFFFu
#define NBLK    ((N_NODES + 255) / 256)   // 391

// ---- static device scratch ----
__device__ __align__(16) __half g_h16[N_NODES * HID];  // fp16 features for gather
__device__ __align__(16) float  g_x2[N_NODES * HID];   // layer-1 output
__device__ float    g_as[N_NODES];
__device__ float    g_ad[N_NODES];
__device__ int      g_deg[N_NODES];
__device__ int      g_off[N_NODES];
__device__ int      g_cur[N_NODES];
__device__ int      g_csr[N_EDGES];
__device__ int      g_part[NBLK];
__device__ unsigned g_amax_enc[2];
__device__ float    g_ws2[HID], g_wd2[HID];            // W2 @ att_{src,dst}2

__device__ __forceinline__ unsigned encf(float f) {
    unsigned u = __float_as_uint(f);
    return (u & 0x80000000u) ? ~u : (u | 0x80000000u);
}
__device__ __forceinline__ float decf(unsigned u) {
    return (u & 0x80000000u) ? __uint_as_float(u ^ 0x80000000u)
                             : __uint_as_float(~u);
}
__device__ __forceinline__ float lrelu(float x) { return x >= 0.f ? x : NEG * x; }

__device__ __forceinline__ void block_amax(float s_lane0, int lane, int wid, int slot) {
    __shared__ float warp_s[8];
    if (lane == 0) warp_s[wid] = s_lane0;
    __syncthreads();
    if (wid == 0 && lane == 0) {
        float m = warp_s[0];
#pragma unroll
        for (int i = 1; i < 8; i++) m = fmaxf(m, warp_s[i]);
        atomicMax(&g_amax_enc[slot], encf(m));
    }
}

// ---------------------------------------------------------------------------
// tiny precompute: amax init + ws2/wd2 = W2 @ att vectors (one warp)
// ---------------------------------------------------------------------------
__global__ void k_precomp(const float* __restrict__ W2,
                          const float* __restrict__ as2,
                          const float* __restrict__ ad2) {
    int i = threadIdx.x;
    if (i == 0) { g_amax_enc[0] = ENC_NEGINF; g_amax_enc[1] = ENC_NEGINF; }
    float ws = 0.f, wd = 0.f;
#pragma unroll
    for (int j = 0; j < HID; j++) {
        float w = W2[i * HID + j];
        ws += w * as2[j];
        wd += w * ad2[j];
    }
    g_ws2[i] = ws;
    g_wd2[i] = wd;
}

__global__ void __launch_bounds__(256) k_zero_deg() {
    int i = blockIdx.x * 256 + threadIdx.x;
    if (i < N_NODES) g_deg[i] = 0;
}

__global__ void __launch_bounds__(256) k_count(const int* __restrict__ dst) {
    int e = blockIdx.x * 256 + threadIdx.x;
    if (e < N_EDGES) atomicAdd(&g_deg[dst[e]], 1);
}

// block-level exclusive scan of degrees; g_part[b] = block sum
__global__ void __launch_bounds__(256) k_scan1() {
    __shared__ int s[256];
    int t = threadIdx.x;
    int idx = blockIdx.x * 256 + t;
    int v = (idx < N_NODES) ? g_deg[idx] : 0;
    s[t] = v;
    __syncthreads();
#pragma unroll
    for (int o = 1; o < 256; o <<= 1) {
        int a = 0;
        if (t >= o) a = s[t - o];
        __syncthreads();
        if (t >= o) s[t] += a;
        __syncthreads();
    }
    if (idx < N_NODES) g_off[idx] = s[t] - v;     // exclusive within block
    if (t == 255) g_part[blockIdx.x] = s[255];
}

__global__ void k_scan2() {   // <<<1,512>>> exclusive scan of g_part
    __shared__ int s[512];
    int t = threadIdx.x;
    int v = (t < NBLK) ? g_part[t] : 0;
    s[t] = v;
    __syncthreads();
#pragma unroll
    for (int o = 1; o < 512; o <<= 1) {
        int a = 0;
        if (t >= o) a = s[t - o];
        __syncthreads();
        if (t >= o) s[t] += a;
        __syncthreads();
    }
    if (t < NBLK) g_part[t] = s[t] - v;
}

__global__ void __launch_bounds__(256) k_scan3() {
    int idx = blockIdx.x * 256 + threadIdx.x;
    if (idx < N_NODES) {
        int o = g_off[idx] + g_part[blockIdx.x];
        g_off[idx] = o;
        g_cur[idx] = o;
    }
}

__global__ void __launch_bounds__(256) k_fill(const int* __restrict__ src,
                                              const int* __restrict__ dst) {
    int e = blockIdx.x * 256 + threadIdx.x;
    if (e < N_EDGES) {
        int d = dst[e];
        int slot = atomicAdd(&g_cur[d], 1);
        g_csr[slot] = src[e];
    }
}

// ---------------------------------------------------------------------------
// Layer 1 transform: h = x @ W1 (fp16 store); a_s/a_d; amax slot 0.
// ---------------------------------------------------------------------------
__global__ void __launch_bounds__(256) k_transform1(
    const float* __restrict__ x, const float* __restrict__ W1,
    const float* __restrict__ aw_s, const float* __restrict__ aw_d)
{
    int wid  = threadIdx.x >> 5;
    int lane = threadIdx.x & 31;
    int node = blockIdx.x * 8 + wid;

    float s = -3.4e38f;
    if (node < N_NODES) {
        float xv = (lane < 3) ? x[node * 3 + lane] : 0.f;
        float x0 = __shfl_sync(0xffffffffu, xv, 0);
        float x1 = __shfl_sync(0xffffffffu, xv, 1);
        float x2 = __shfl_sync(0xffffffffu, xv, 2);

        float h = x0 * W1[lane] + x1 * W1[HID + lane] + x2 * W1[2 * HID + lane];
        g_h16[node * HID + lane] = __float2half(h);

        s = h * aw_s[lane];
        float d = h * aw_d[lane];
#pragma unroll
        for (int o = 16; o; o >>= 1) {
            s += __shfl_xor_sync(0xffffffffu, s, o);
            d += __shfl_xor_sync(0xffffffffu, d, o);
        }
        if (lane == 0) { g_as[node] = s; g_ad[node] = d; }
    }
    block_amax(s, lane, wid, 0);
}

// ---------------------------------------------------------------------------
// CSR gather core: returns softmax-weighted feature sum for this node's lane.
// exp computed once per edge (prefetch lane), broadcast via shfl.
// ---------------------------------------------------------------------------
template<int SLOT>
__device__ __forceinline__ float gather_node(int node, int lane) {
    const float Amax = decf(g_amax_enc[SLOT]);
    const float ad   = g_ad[node];
    const float m    = lrelu(Amax + ad);

    int begin = g_off[node];
    int deg   = g_deg[node];

    float acc = 0.f;
    float denp = 0.f;   // per-lane partial of denominator (from prefetch lanes)

    for (int base = 0; base < deg; base += 32) {
        int idx = base + lane;
        int valid = idx < deg;
        int   sj = valid ? g_csr[begin + idx] : 0;
        float ex = 0.f;
        if (valid) {
            float a = g_as[sj];
            ex = __expf(lrelu(a + ad) - m);
            denp += ex;
        }
        int cnt = deg - base;
        if (cnt >= 32) {
#pragma unroll
            for (int j = 0; j < 32; j++) {
                int   s = __shfl_sync(0xffffffffu, sj, j);
                float e = __shfl_sync(0xffffffffu, ex, j);
                acc += e * __half2float(g_h16[s * HID + lane]);
            }
        } else {
            for (int j = 0; j < cnt; j++) {
                int   s = __shfl_sync(0xffffffffu, sj, j);
                float e = __shfl_sync(0xffffffffu, ex, j);
                acc += e * __half2float(g_h16[s * HID + lane]);
            }
        }
    }
    // self-loop term
    float exs = __expf(lrelu(g_as[node] + ad) - m);
    acc  += exs * __half2float(g_h16[node * HID + lane]);
    denp += (lane == 0) ? exs : 0.f;

    // reduce denominator across lanes
    float den = denp;
#pragma unroll
    for (int o = 16; o; o >>= 1) den += __shfl_xor_sync(0xffffffffu, den, o);

    return acc / (den + 1e-16f);
}

// Layer-1 gather + epilogue: x2 = relu(agg + b1)
__global__ void __launch_bounds__(256) k_gather1(const float* __restrict__ b1) {
    int warp = (blockIdx.x * 256 + threadIdx.x) >> 5;
    int lane = threadIdx.x & 31;
    if (warp >= N_NODES) return;
    float v = gather_node<0>(warp, lane) + b1[lane];
    g_x2[warp * HID + lane] = v > 0.f ? v : 0.f;
}

// ---------------------------------------------------------------------------
// Layer-2 transform: h2 = x2 @ W2 via smem staging; reductions use precomputed
// ws2/wd2 so they run on the pre-matmul vector. amax slot 1.
// ---------------------------------------------------------------------------
__global__ void __launch_bounds__(256) k_transform2(const float* __restrict__ W2) {
    __shared__ float sW2[HID * HID];
    __shared__ float sx[256];
    for (int i = threadIdx.x; i < HID * HID; i += 256) sW2[i] = W2[i];
    __syncthreads();

    int wid  = threadIdx.x >> 5;
    int lane = threadIdx.x & 31;
    int node = blockIdx.x * 8 + wid;

    float s = -3.4e38f;
    if (node < N_NODES) {
        float v = g_x2[node * HID + lane];

        // a_s2 / a_d2 via precomputed W2@att vectors (no dependence on h)
        s = v * g_ws2[lane];
        float d = v * g_wd2[lane];
#pragma unroll
        for (int o = 16; o; o >>= 1) {
            s += __shfl_xor_sync(0xffffffffu, s, o);
            d += __shfl_xor_sync(0xffffffffu, d, o);
        }
        if (lane == 0) { g_as[node] = s; g_ad[node] = d; }

        sx[threadIdx.x] = v;
        __syncwarp();

        float h = 0.f;
#pragma unroll
        for (int i = 0; i < HID; i++)
            h += sx[wid * HID + i] * sW2[i * HID + lane];

        g_h16[node * HID + lane] = __float2half(h);
    }
    block_amax(s, lane, wid, 1);
}

// Layer-2 gather + epilogue + linear head: out[n] = relu(agg+b2) . Wl + bl
__global__ void __launch_bounds__(256) k_gather2(
    const float* __restrict__ b2, const float* __restrict__ Wl,
    const float* __restrict__ bl, float* __restrict__ out)
{
    int warp = (blockIdx.x * 256 + threadIdx.x) >> 5;
    int lane = threadIdx.x & 31;
    if (warp >= N_NODES) return;
    float v = gather_node<1>(warp, lane) + b2[lane];
    v = v > 0.f ? v : 0.f;
    float p = v * Wl[lane];
#pragma unroll
    for (int o = 16; o; o >>= 1) p += __shfl_xor_sync(0xffffffffu, p, o);
    if (lane == 0) out[warp] = p + bl[0];
}

// ---------------------------------------------------------------------------
extern "C" void kernel_launch(void* const* d_in, const int* in_sizes, int n_in,
                              void* d_out, int out_size)
{
    const float* x   = (const float*)d_in[0];
    const int*  eidx = (const int*)d_in[1];     // [2, E]
    const float* W1  = (const float*)d_in[2];
    const float* as1 = (const float*)d_in[3];
    const float* ad1 = (const float*)d_in[4];
    const float* b1  = (const float*)d_in[5];
    const float* W2  = (const float*)d_in[6];
    const float* as2 = (const float*)d_in[7];
    const float* ad2 = (const float*)d_in[8];
    const float* b2  = (const float*)d_in[9];
    const float* Wl  = (const float*)d_in[10];
    const float* bl  = (const float*)d_in[11];
    float*       out = (float*)d_out;

    const int* src = eidx;
    const int* dst = eidx + N_EDGES;

    const int nodeBlocks = (N_NODES + 7) / 8;       // warp per node
    const int edgeBlocks = (N_EDGES + 255) / 256;

    // ---- CSR build (shared by both layers) ----
    k_precomp<<<1, 32>>>(W2, as2, ad2);
    k_zero_deg<<<NBLK, 256>>>();
    k_count<<<edgeBlocks, 256>>>(dst);
    k_scan1<<<NBLK, 256>>>();
    k_scan2<<<1, 512>>>();
    k_scan3<<<NBLK, 256>>>();
    k_fill<<<edgeBlocks, 256>>>(src, dst);

    // ---- layer 1 ----
    k_transform1<<<nodeBlocks, 256>>>(x, W1, as1, ad1);
    k_gather1<<<nodeBlocks, 256>>>(b1);

    // ---- layer 2 ----
    k_transform2<<<nodeBlocks, 256>>>(W2);
    k_gather2<<<nodeBlocks, 256>>>(b2, Wl, bl, out);
}

// round 5
// speedup vs baseline: 1.9760x; 1.2235x over previous
#include <cuda_runtime.h>
#include <cuda_fp16.h>

#define N_NODES 100000
#define N_EDGES 3200000
#define HID     32
#define NEG     0.2f
#define ENC_NEGINF 0x007FFFFFu
#define NBLK    ((N_NODES + 255) / 256)   // 391

// ---- static device scratch ----
__device__ __align__(16) __half g_h16[N_NODES * HID];  // fp16 features for gather
__device__ __align__(16) float  g_x2[N_NODES * HID];   // layer-1 output
__device__ float    g_as[N_NODES];
__device__ float    g_ad[N_NODES];
__device__ int      g_deg[N_NODES];
__device__ int      g_off[N_NODES];
__device__ int      g_cur[N_NODES];
__device__ int      g_csr[N_EDGES];
__device__ int      g_part[NBLK];
__device__ unsigned g_amax_enc[2];
__device__ float    g_ws2[HID], g_wd2[HID];            // W2 @ att_{src,dst}2

__device__ __forceinline__ unsigned encf(float f) {
    unsigned u = __float_as_uint(f);
    return (u & 0x80000000u) ? ~u : (u | 0x80000000u);
}
__device__ __forceinline__ float decf(unsigned u) {
    return (u & 0x80000000u) ? __uint_as_float(u ^ 0x80000000u)
                             : __uint_as_float(~u);
}
__device__ __forceinline__ float lrelu(float x) { return x >= 0.f ? x : NEG * x; }

__device__ __forceinline__ void block_amax(float s_lane0, int lane, int wid, int slot) {
    __shared__ float warp_s[8];
    if (lane == 0) warp_s[wid] = s_lane0;
    __syncthreads();
    if (wid == 0 && lane == 0) {
        float m = warp_s[0];
#pragma unroll
        for (int i = 1; i < 8; i++) m = fmaxf(m, warp_s[i]);
        atomicMax(&g_amax_enc[slot], encf(m));
    }
}

// ---------------------------------------------------------------------------
__global__ void k_precomp(const float* __restrict__ W2,
                          const float* __restrict__ as2,
                          const float* __restrict__ ad2) {
    int i = threadIdx.x;
    if (i == 0) { g_amax_enc[0] = ENC_NEGINF; g_amax_enc[1] = ENC_NEGINF; }
    float ws = 0.f, wd = 0.f;
#pragma unroll
    for (int j = 0; j < HID; j++) {
        float w = W2[i * HID + j];
        ws += w * as2[j];
        wd += w * ad2[j];
    }
    g_ws2[i] = ws;
    g_wd2[i] = wd;
}

__global__ void __launch_bounds__(256) k_zero_deg() {
    int i = blockIdx.x * 256 + threadIdx.x;
    if (i < N_NODES) g_deg[i] = 0;
}

__global__ void __launch_bounds__(256) k_count(const int* __restrict__ dst) {
    int e = blockIdx.x * 256 + threadIdx.x;
    if (e < N_EDGES) atomicAdd(&g_deg[dst[e]], 1);
}

__global__ void __launch_bounds__(256) k_scan1() {
    __shared__ int s[256];
    int t = threadIdx.x;
    int idx = blockIdx.x * 256 + t;
    int v = (idx < N_NODES) ? g_deg[idx] : 0;
    s[t] = v;
    __syncthreads();
#pragma unroll
    for (int o = 1; o < 256; o <<= 1) {
        int a = 0;
        if (t >= o) a = s[t - o];
        __syncthreads();
        if (t >= o) s[t] += a;
        __syncthreads();
    }
    if (idx < N_NODES) g_off[idx] = s[t] - v;
    if (t == 255) g_part[blockIdx.x] = s[255];
}

__global__ void k_scan2() {   // <<<1,512>>>
    __shared__ int s[512];
    int t = threadIdx.x;
    int v = (t < NBLK) ? g_part[t] : 0;
    s[t] = v;
    __syncthreads();
#pragma unroll
    for (int o = 1; o < 512; o <<= 1) {
        int a = 0;
        if (t >= o) a = s[t - o];
        __syncthreads();
        if (t >= o) s[t] += a;
        __syncthreads();
    }
    if (t < NBLK) g_part[t] = s[t] - v;
}

__global__ void __launch_bounds__(256) k_scan3() {
    int idx = blockIdx.x * 256 + threadIdx.x;
    if (idx < N_NODES) {
        int o = g_off[idx] + g_part[blockIdx.x];
        g_off[idx] = o;
        g_cur[idx] = o;
    }
}

__global__ void __launch_bounds__(256) k_fill(const int* __restrict__ src,
                                              const int* __restrict__ dst) {
    int e = blockIdx.x * 256 + threadIdx.x;
    if (e < N_EDGES) {
        int d = dst[e];
        int slot = atomicAdd(&g_cur[d], 1);
        g_csr[slot] = src[e];
    }
}

// ---------------------------------------------------------------------------
// Layer 1 transform: h = x @ W1 (fp16 store); a_s/a_d; amax slot 0.
// ---------------------------------------------------------------------------
__global__ void __launch_bounds__(256) k_transform1(
    const float* __restrict__ x, const float* __restrict__ W1,
    const float* __restrict__ aw_s, const float* __restrict__ aw_d)
{
    int wid  = threadIdx.x >> 5;
    int lane = threadIdx.x & 31;
    int node = blockIdx.x * 8 + wid;

    float s = -3.4e38f;
    if (node < N_NODES) {
        float xv = (lane < 3) ? x[node * 3 + lane] : 0.f;
        float x0 = __shfl_sync(0xffffffffu, xv, 0);
        float x1 = __shfl_sync(0xffffffffu, xv, 1);
        float x2 = __shfl_sync(0xffffffffu, xv, 2);

        float h = x0 * W1[lane] + x1 * W1[HID + lane] + x2 * W1[2 * HID + lane];
        g_h16[node * HID + lane] = __float2half(h);

        s = h * aw_s[lane];
        float d = h * aw_d[lane];
#pragma unroll
        for (int o = 16; o; o >>= 1) {
            s += __shfl_xor_sync(0xffffffffu, s, o);
            d += __shfl_xor_sync(0xffffffffu, d, o);
        }
        if (lane == 0) { g_as[node] = s; g_ad[node] = d; }
    }
    block_amax(s, lane, wid, 0);
}

// ---------------------------------------------------------------------------
// Half-warp-per-node CSR gather. Each half (16 lanes) owns one node; lane
// handles features {2*hl, 2*hl+1} via half2 loads. Per 16-edge chunk: lanes
// compute (src, ex) pairs, stage to smem, then a fully-unrolled loop does one
// broadcast LDS.64 + one half2 LDG + 2 FFMA per edge. Loop runs to the max
// degree of the warp's two nodes so __syncwarp stays convergent; padded lanes
// carry ex=0.
// ---------------------------------------------------------------------------
template<int SLOT>
__device__ __forceinline__ float2 gather_half(int node, int hl, int half,
                                              float2* __restrict__ st,
                                              int degmax)
{
    const float Amax = decf(g_amax_enc[SLOT]);
    const float ad   = g_ad[node];
    const float m    = lrelu(Amax + ad);
    const int begin  = g_off[node];
    const int deg    = g_deg[node];

    float accx = 0.f, accy = 0.f, denp = 0.f;

    for (int base = 0; base < degmax; base += 16) {
        int idx = base + hl;
        int sj = 0;
        float ex = 0.f;
        if (idx < deg) {
            sj = g_csr[begin + idx];
            ex = __expf(lrelu(g_as[sj] + ad) - m);
            denp += ex;
        }
        st[hl * 2 + half] = make_float2(__int_as_float(sj), ex);
        __syncwarp();
#pragma unroll
        for (int j = 0; j < 16; j++) {
            float2 p = st[j * 2 + half];        // broadcast LDS.64 per half
            int   s  = __float_as_int(p.x);
            float e  = p.y;
            half2 hv = *reinterpret_cast<const half2*>(&g_h16[s * HID + hl * 2]);
            float2 f = __half22float2(hv);
            accx += e * f.x;
            accy += e * f.y;
        }
        __syncwarp();
    }

    // self-loop
    {
        float exs = __expf(lrelu(g_as[node] + ad) - m);
        half2 hv = *reinterpret_cast<const half2*>(&g_h16[node * HID + hl * 2]);
        float2 f = __half22float2(hv);
        accx += exs * f.x;
        accy += exs * f.y;
        if (hl == 0) denp += exs;
    }

    // denominator reduce within the 16-lane half
#pragma unroll
    for (int o = 8; o; o >>= 1) denp += __shfl_xor_sync(0xffffffffu, denp, o);
    float r = 1.f / (denp + 1e-16f);
    return make_float2(accx * r, accy * r);
}

// Layer-1 gather + epilogue: x2 = relu(agg + b1).  16 nodes per 256-thr block.
__global__ void __launch_bounds__(256) k_gather1(const float* __restrict__ b1) {
    __shared__ float2 stage[8][32];
    int wid  = threadIdx.x >> 5;
    int lane = threadIdx.x & 31;
    int half = lane >> 4;
    int hl   = lane & 15;
    int node = (blockIdx.x * 8 + wid) * 2 + half;   // N_NODES = 6250*16 exactly

    int deg = g_deg[node];
    int degmax = max(deg, __shfl_xor_sync(0xffffffffu, deg, 16));

    float2 v = gather_half<0>(node, hl, half, stage[wid], degmax);
    float vx = v.x + b1[hl * 2];
    float vy = v.y + b1[hl * 2 + 1];
    g_x2[node * HID + hl * 2]     = vx > 0.f ? vx : 0.f;
    g_x2[node * HID + hl * 2 + 1] = vy > 0.f ? vy : 0.f;
}

// ---------------------------------------------------------------------------
// Layer-2 transform: h2 = x2 @ W2 via smem staging; attention halves via
// precomputed ws2/wd2 on the pre-matmul vector. amax slot 1.
// ---------------------------------------------------------------------------
__global__ void __launch_bounds__(256) k_transform2(const float* __restrict__ W2) {
    __shared__ float sW2[HID * HID];
    __shared__ float sx[256];
    for (int i = threadIdx.x; i < HID * HID; i += 256) sW2[i] = W2[i];
    __syncthreads();

    int wid  = threadIdx.x >> 5;
    int lane = threadIdx.x & 31;
    int node = blockIdx.x * 8 + wid;

    float s = -3.4e38f;
    if (node < N_NODES) {
        float v = g_x2[node * HID + lane];

        s = v * g_ws2[lane];
        float d = v * g_wd2[lane];
#pragma unroll
        for (int o = 16; o; o >>= 1) {
            s += __shfl_xor_sync(0xffffffffu, s, o);
            d += __shfl_xor_sync(0xffffffffu, d, o);
        }
        if (lane == 0) { g_as[node] = s; g_ad[node] = d; }

        sx[threadIdx.x] = v;
        __syncwarp();

        float h = 0.f;
#pragma unroll
        for (int i = 0; i < HID; i++)
            h += sx[wid * HID + i] * sW2[i * HID + lane];

        g_h16[node * HID + lane] = __float2half(h);
    }
    block_amax(s, lane, wid, 1);
}

// Layer-2 gather + epilogue + linear head.
__global__ void __launch_bounds__(256) k_gather2(
    const float* __restrict__ b2, const float* __restrict__ Wl,
    const float* __restrict__ bl, float* __restrict__ out)
{
    __shared__ float2 stage[8][32];
    int wid  = threadIdx.x >> 5;
    int lane = threadIdx.x & 31;
    int half = lane >> 4;
    int hl   = lane & 15;
    int node = (blockIdx.x * 8 + wid) * 2 + half;

    int deg = g_deg[node];
    int degmax = max(deg, __shfl_xor_sync(0xffffffffu, deg, 16));

    float2 v = gather_half<1>(node, hl, half, stage[wid], degmax);
    float vx = v.x + b2[hl * 2];
    float vy = v.y + b2[hl * 2 + 1];
    vx = vx > 0.f ? vx : 0.f;
    vy = vy > 0.f ? vy : 0.f;
    float p = vx * Wl[hl * 2] + vy * Wl[hl * 2 + 1];
#pragma unroll
    for (int o = 8; o; o >>= 1) p += __shfl_xor_sync(0xffffffffu, p, o);
    if (hl == 0) out[node] = p + bl[0];
}

// ---------------------------------------------------------------------------
extern "C" void kernel_launch(void* const* d_in, const int* in_sizes, int n_in,
                              void* d_out, int out_size)
{
    const float* x   = (const float*)d_in[0];
    const int*  eidx = (const int*)d_in[1];     // [2, E]
    const float* W1  = (const float*)d_in[2];
    const float* as1 = (const float*)d_in[3];
    const float* ad1 = (const float*)d_in[4];
    const float* b1  = (const float*)d_in[5];
    const float* W2  = (const float*)d_in[6];
    const float* as2 = (const float*)d_in[7];
    const float* ad2 = (const float*)d_in[8];
    const float* b2  = (const float*)d_in[9];
    const float* Wl  = (const float*)d_in[10];
    const float* bl  = (const float*)d_in[11];
    float*       out = (float*)d_out;

    const int* src = eidx;
    const int* dst = eidx + N_EDGES;

    const int nodeBlocks   = (N_NODES + 7) / 8;       // warp per node (transforms)
    const int gatherBlocks = (N_NODES + 15) / 16;     // half-warp per node (gathers)
    const int edgeBlocks   = (N_EDGES + 255) / 256;

    // ---- CSR build (shared by both layers) ----
    k_precomp<<<1, 32>>>(W2, as2, ad2);
    k_zero_deg<<<NBLK, 256>>>();
    k_count<<<edgeBlocks, 256>>>(dst);
    k_scan1<<<NBLK, 256>>>();
    k_scan2<<<1, 512>>>();
    k_scan3<<<NBLK, 256>>>();
    k_fill<<<edgeBlocks, 256>>>(src, dst);

    // ---- layer 1 ----
    k_transform1<<<nodeBlocks, 256>>>(x, W1, as1, ad1);
    k_gather1<<<gatherBlocks, 256>>>(b1);

    // ---- layer 2 ----
    k_transform2<<<nodeBlocks, 256>>>(W2);
    k_gather2<<<gatherBlocks, 256>>>(b2, Wl, bl, out);
}

// round 6
// speedup vs baseline: 2.0632x; 1.0442x over previous
#include <cuda_runtime.h>
#include <cuda_fp16.h>

#define N_NODES 100000
#define N_EDGES 3200000
#define HID     32
#define NEG     0.2f
#define ENC_NEGINF 0x007FFFFFu
#define NBLK        ((N_NODES + 255) / 256)   // 391
#define NODE_BLOCKS ((N_NODES + 7) / 8)       // 12500 (transform part of k_p1)
#define EDGE_BLOCKS ((N_EDGES + 255) / 256)   // 12500 (count part of k_p1)
#define GATHER_BLOCKS (N_NODES / 16)          // 6250 (100000 = 6250*16 exactly)

// ---- static device scratch ----
__device__ __align__(16) __half g_h16 [N_NODES * HID];  // layer-1 features (fp16)
__device__ __align__(16) __half g_h16b[N_NODES * HID];  // layer-2 features (fp16)
__device__ float    g_as [N_NODES], g_ad [N_NODES];     // layer-1 attention halves
__device__ float    g_as2[N_NODES], g_ad2[N_NODES];     // layer-2 attention halves
__device__ int      g_deg[N_NODES];
__device__ int      g_off[N_NODES];
__device__ int      g_cur[N_NODES];
__device__ int      g_csr[N_EDGES];
__device__ int      g_base;                             // atomic scan base
__device__ unsigned g_amax_enc[2];
__device__ float    g_ws2[HID], g_wd2[HID];             // W2 @ att_{src,dst}2

__device__ __forceinline__ unsigned encf(float f) {
    unsigned u = __float_as_uint(f);
    return (u & 0x80000000u) ? ~u : (u | 0x80000000u);
}
__device__ __forceinline__ float decf(unsigned u) {
    return (u & 0x80000000u) ? __uint_as_float(u ^ 0x80000000u)
                             : __uint_as_float(~u);
}
__device__ __forceinline__ float lrelu(float x) { return x >= 0.f ? x : NEG * x; }

// ---------------------------------------------------------------------------
// precompute: amax/scan-base init + ws2/wd2 = W2 @ att vectors (one warp)
// ---------------------------------------------------------------------------
__global__ void k_precomp(const float* __restrict__ W2,
                          const float* __restrict__ as2,
                          const float* __restrict__ ad2) {
    int i = threadIdx.x;
    if (i == 0) {
        g_amax_enc[0] = ENC_NEGINF;
        g_amax_enc[1] = ENC_NEGINF;
        g_base = 0;
    }
    float ws = 0.f, wd = 0.f;
#pragma unroll
    for (int j = 0; j < HID; j++) {
        float w = W2[i * HID + j];
        ws += w * as2[j];
        wd += w * ad2[j];
    }
    g_ws2[i] = ws;
    g_wd2[i] = wd;
}

// ---------------------------------------------------------------------------
// Phase 1 (fused, independent halves): blocks [0, NODE_BLOCKS) run the layer-1
// transform (h1 = x@W1, a_s/a_d, amax slot 0); blocks [NODE_BLOCKS, ..) run the
// degree count. The two memory streams overlap instead of serializing.
// ---------------------------------------------------------------------------
__global__ void __launch_bounds__(256) k_p1(
    const float* __restrict__ x, const float* __restrict__ W1,
    const float* __restrict__ aw_s, const float* __restrict__ aw_d,
    const int* __restrict__ dst)
{
    if (blockIdx.x >= NODE_BLOCKS) {
        int e = (blockIdx.x - NODE_BLOCKS) * 256 + threadIdx.x;
        if (e < N_EDGES) atomicAdd(&g_deg[dst[e]], 1);
        return;
    }

    int wid  = threadIdx.x >> 5;
    int lane = threadIdx.x & 31;
    int node = blockIdx.x * 8 + wid;

    float s = -3.4e38f;
    if (node < N_NODES) {
        float xv = (lane < 3) ? x[node * 3 + lane] : 0.f;
        float x0 = __shfl_sync(0xffffffffu, xv, 0);
        float x1 = __shfl_sync(0xffffffffu, xv, 1);
        float x2 = __shfl_sync(0xffffffffu, xv, 2);

        float h = x0 * W1[lane] + x1 * W1[HID + lane] + x2 * W1[2 * HID + lane];
        g_h16[node * HID + lane] = __float2half(h);

        s = h * aw_s[lane];
        float d = h * aw_d[lane];
#pragma unroll
        for (int o = 16; o; o >>= 1) {
            s += __shfl_xor_sync(0xffffffffu, s, o);
            d += __shfl_xor_sync(0xffffffffu, d, o);
        }
        if (lane == 0) { g_as[node] = s; g_ad[node] = d; }
    }
    // block max of s -> amax slot 0
    __shared__ float warp_s[8];
    if (lane == 0) warp_s[wid] = s;
    __syncthreads();
    if (threadIdx.x == 0) {
        float m = warp_s[0];
#pragma unroll
        for (int i = 1; i < 8; i++) m = fmaxf(m, warp_s[i]);
        atomicMax(&g_amax_enc[0], encf(m));
    }
}

// ---------------------------------------------------------------------------
// Single-kernel scan: block-local exclusive scan + atomic block base.
// Ranges are disjoint; assignment order is irrelevant to correctness.
// ---------------------------------------------------------------------------
__global__ void __launch_bounds__(256) k_scan() {
    __shared__ int s[256];
    __shared__ int sbase;
    int t = threadIdx.x;
    int idx = blockIdx.x * 256 + t;
    int v = (idx < N_NODES) ? g_deg[idx] : 0;
    s[t] = v;
    __syncthreads();
#pragma unroll
    for (int o = 1; o < 256; o <<= 1) {
        int a = 0;
        if (t >= o) a = s[t - o];
        __syncthreads();
        if (t >= o) s[t] += a;
        __syncthreads();
    }
    if (t == 255) sbase = atomicAdd(&g_base, s[255]);
    __syncthreads();
    if (idx < N_NODES) {
        int o = sbase + s[t] - v;
        g_off[idx] = o;
        g_cur[idx] = o;
    }
}

__global__ void __launch_bounds__(256) k_fill(const int* __restrict__ src,
                                              const int* __restrict__ dst) {
    int e = blockIdx.x * 256 + threadIdx.x;
    if (e < N_EDGES) {
        int d = dst[e];
        int slot = atomicAdd(&g_cur[d], 1);
        g_csr[slot] = src[e];
    }
}

// ---------------------------------------------------------------------------
// Software-pipelined half-warp CSR gather. 16 lanes own one node, lane handles
// features {2hl, 2hl+1} (half2). While the 16-edge consume loop of chunk k
// streams feature rows, the (csr, a_s, exp) loads of chunk k+1 are in flight.
// ---------------------------------------------------------------------------
__device__ __forceinline__ float2 gather_half(
    int node, int hl, int half, float2* __restrict__ st, int degmax,
    const float* __restrict__ asv, const float* __restrict__ adv,
    const __half* __restrict__ hbuf, float Amax)
{
    const float ad = adv[node];
    const float m  = lrelu(Amax + ad);
    const int begin = g_off[node];
    const int deg   = g_deg[node];

    float accx = 0.f, accy = 0.f, denp = 0.f;

    // prologue: chunk 0 edge for this lane
    int sj = 0; float ex = 0.f;
    if (hl < deg) {
        sj = g_csr[begin + hl];
        ex = __expf(lrelu(asv[sj] + ad) - m);
    }

    for (int base = 0; base < degmax; base += 16) {
        denp += ex;
        st[hl * 2 + half] = make_float2(__int_as_float(sj), ex);
        __syncwarp();

        // prefetch chunk k+1 (overlaps with consume below)
        int nidx = base + 16 + hl;
        int nsj = 0; float nex = 0.f;
        if (nidx < deg) {
            nsj = g_csr[begin + nidx];
            nex = __expf(lrelu(asv[nsj] + ad) - m);
        }

        // consume chunk k
#pragma unroll
        for (int j = 0; j < 16; j++) {
            float2 p = st[j * 2 + half];
            int   sE = __float_as_int(p.x);
            float e  = p.y;
            half2 hv = *reinterpret_cast<const half2*>(&hbuf[sE * HID + hl * 2]);
            float2 f = __half22float2(hv);
            accx += e * f.x;
            accy += e * f.y;
        }
        __syncwarp();
        sj = nsj; ex = nex;
    }

    // self-loop
    {
        float exs = __expf(lrelu(asv[node] + ad) - m);
        half2 hv = *reinterpret_cast<const half2*>(&hbuf[node * HID + hl * 2]);
        float2 f = __half22float2(hv);
        accx += exs * f.x;
        accy += exs * f.y;
        if (hl == 0) denp += exs;
    }

#pragma unroll
    for (int o = 8; o; o >>= 1) denp += __shfl_xor_sync(0xffffffffu, denp, o);
    float r = 1.f / (denp + 1e-16f);
    return make_float2(accx * r, accy * r);
}

// ---------------------------------------------------------------------------
// Fused: layer-1 gather + relu/bias epilogue + layer-2 transform (x2@W2),
// layer-2 attention halves via precomputed ws2/wd2, amax slot 1.
// Layer-2 outputs go to separate buffers (g_h16b/g_as2/g_ad2) to avoid racing
// blocks still gathering layer-1 data.
// ---------------------------------------------------------------------------
__global__ void __launch_bounds__(256) k_g1t2(
    const float* __restrict__ W2, const float* __restrict__ b1)
{
    __shared__ float2 stage[8][32];
    __shared__ float  sW2[HID * HID];
    __shared__ float  sxw[8][64];

    for (int i = threadIdx.x; i < HID * HID; i += 256) sW2[i] = W2[i];
    __syncthreads();

    int wid  = threadIdx.x >> 5;
    int lane = threadIdx.x & 31;
    int half = lane >> 4;
    int hl   = lane & 15;
    int node = (blockIdx.x * 8 + wid) * 2 + half;

    int deg = g_deg[node];
    int degmax = max(deg, __shfl_xor_sync(0xffffffffu, deg, 16));

    float Amax0 = decf(g_amax_enc[0]);
    float2 v = gather_half(node, hl, half, stage[wid], degmax,
                           g_as, g_ad, g_h16, Amax0);
    float vx = v.x + b1[hl * 2];
    float vy = v.y + b1[hl * 2 + 1];
    vx = vx > 0.f ? vx : 0.f;
    vy = vy > 0.f ? vy : 0.f;

    // layer-2 attention halves on x2 (pre-matmul, via W2@att vectors)
    float s = vx * g_ws2[hl * 2] + vy * g_ws2[hl * 2 + 1];
    float d = vx * g_wd2[hl * 2] + vy * g_wd2[hl * 2 + 1];
#pragma unroll
    for (int o = 8; o; o >>= 1) {
        s += __shfl_xor_sync(0xffffffffu, s, o);
        d += __shfl_xor_sync(0xffffffffu, d, o);
    }
    if (hl == 0) { g_as2[node] = s; g_ad2[node] = d; }

    // layer-2 transform: h2 = x2 @ W2 within the half-warp
    sxw[wid][half * 32 + hl * 2]     = vx;
    sxw[wid][half * 32 + hl * 2 + 1] = vy;
    __syncwarp();
    float h0 = 0.f, h1 = 0.f;
#pragma unroll
    for (int i = 0; i < HID; i++) {
        float xi = sxw[wid][half * 32 + i];
        float2 w = *reinterpret_cast<const float2*>(&sW2[i * HID + hl * 2]);
        h0 += xi * w.x;
        h1 += xi * w.y;
    }
    *reinterpret_cast<half2*>(&g_h16b[node * HID + hl * 2]) =
        __floats2half2_rn(h0, h1);

    // amax slot 1 (s is uniform across each half after the reduce)
    __shared__ float wmax[8];
    float mw = fmaxf(s, __shfl_xor_sync(0xffffffffu, s, 16));
    if (lane == 0) wmax[wid] = mw;
    __syncthreads();
    if (threadIdx.x == 0) {
        float mb = wmax[0];
#pragma unroll
        for (int i = 1; i < 8; i++) mb = fmaxf(mb, wmax[i]);
        atomicMax(&g_amax_enc[1], encf(mb));
    }
}

// ---------------------------------------------------------------------------
// Layer-2 gather + epilogue + linear head.
// ---------------------------------------------------------------------------
__global__ void __launch_bounds__(256) k_gather2(
    const float* __restrict__ b2, const float* __restrict__ Wl,
    const float* __restrict__ bl, float* __restrict__ out)
{
    __shared__ float2 stage[8][32];
    int wid  = threadIdx.x >> 5;
    int lane = threadIdx.x & 31;
    int half = lane >> 4;
    int hl   = lane & 15;
    int node = (blockIdx.x * 8 + wid) * 2 + half;

    int deg = g_deg[node];
    int degmax = max(deg, __shfl_xor_sync(0xffffffffu, deg, 16));

    float Amax1 = decf(g_amax_enc[1]);
    float2 v = gather_half(node, hl, half, stage[wid], degmax,
                           g_as2, g_ad2, g_h16b, Amax1);
    float vx = v.x + b2[hl * 2];
    float vy = v.y + b2[hl * 2 + 1];
    vx = vx > 0.f ? vx : 0.f;
    vy = vy > 0.f ? vy : 0.f;
    float p = vx * Wl[hl * 2] + vy * Wl[hl * 2 + 1];
#pragma unroll
    for (int o = 8; o; o >>= 1) p += __shfl_xor_sync(0xffffffffu, p, o);
    if (hl == 0) out[node] = p + bl[0];
}

// ---------------------------------------------------------------------------
extern "C" void kernel_launch(void* const* d_in, const int* in_sizes, int n_in,
                              void* d_out, int out_size)
{
    const float* x   = (const float*)d_in[0];
    const int*  eidx = (const int*)d_in[1];     // [2, E]
    const float* W1  = (const float*)d_in[2];
    const float* as1 = (const float*)d_in[3];
    const float* ad1 = (const float*)d_in[4];
    const float* b1  = (const float*)d_in[5];
    const float* W2  = (const float*)d_in[6];
    const float* as2 = (const float*)d_in[7];
    const float* ad2 = (const float*)d_in[8];
    const float* b2  = (const float*)d_in[9];
    const float* Wl  = (const float*)d_in[10];
    const float* bl  = (const float*)d_in[11];
    float*       out = (float*)d_out;

    const int* src = eidx;
    const int* dst = eidx + N_EDGES;

    // zero the degree array via a memset node (replaces a kernel)
    void* degPtr = nullptr;
    cudaGetSymbolAddress(&degPtr, g_deg);
    cudaMemsetAsync(degPtr, 0, N_NODES * sizeof(int));

    k_precomp<<<1, 32>>>(W2, as2, ad2);
    k_p1<<<NODE_BLOCKS + EDGE_BLOCKS, 256>>>(x, W1, as1, ad1, dst);
    k_scan<<<NBLK, 256>>>();
    k_fill<<<EDGE_BLOCKS, 256>>>(src, dst);
    k_g1t2<<<GATHER_BLOCKS, 256>>>(W2, b1);
    k_gather2<<<GATHER_BLOCKS, 256>>>(b2, Wl, bl, out);
}